// round 4
// baseline (speedup 1.0000x reference)
#include <cuda_runtime.h>
#include <math.h>

typedef unsigned long long ULL;

#define CDIM   192
#define OC3    576
#define HWDIM  256
#define SHIFT  4
#define NWIN   4096

// ---- shared memory layout (floats) ----
// XS: x window / attention output, px-paired float2 [ch][p2], ch-stride 32 pairs = 12288 floats
// QS: qkv after dwconv, px-paired, ch-stride 66 floats (8B-aligned pairs)  = 576*66 = 38016 floats
// ST: GEMM chunk staging 64ch*64px (4096) overlapped with attn 6*1024 (6144) -> 6144 floats
#define XS_OFF 0
#define QS_OFF 12288
#define ST_OFF (12288 + 38016)
#define SMEM_FLOATS (12288 + 38016 + 6144)   // 56448 floats = 225792 bytes

// duplicated-weight tables: w stored transposed [c][oc] as (w,w) pairs
__device__ __align__(16) float2 g_qkv_wd[CDIM * OC3];
__device__ __align__(16) float2 g_proj_wd[CDIM * CDIM];

__global__ void prep_weights(const float* __restrict__ qkv_w,
                             const float* __restrict__ proj_w)
{
    int i = blockIdx.x * blockDim.x + threadIdx.x;
    if (i < CDIM * OC3) {
        int c = i / OC3, oc = i % OC3;
        float w = qkv_w[(size_t)oc * CDIM + c];
        g_qkv_wd[i] = make_float2(w, w);
    } else {
        int j = i - CDIM * OC3;
        if (j < CDIM * CDIM) {
            int c = j / CDIM, oc = j % CDIM;
            float w = proj_w[(size_t)oc * CDIM + c];
            g_proj_wd[j] = make_float2(w, w);
        }
    }
}

__device__ __forceinline__ void ffma2(ULL& d, ULL a, ULL b)
{
    asm("fma.rn.f32x2 %0, %1, %2, %0;" : "+l"(d) : "l"(a), "l"(b));
}
__device__ __forceinline__ ULL dup2(float a)
{
    ULL r; unsigned u = __float_as_uint(a);
    asm("mov.b64 %0, {%1, %1};" : "=l"(r) : "r"(u));
    return r;
}
__device__ __forceinline__ float2 asf2(ULL v)
{
    float2 f;
    f.x = __uint_as_float((unsigned)(v & 0xffffffffu));
    f.y = __uint_as_float((unsigned)(v >> 32));
    return f;
}

// 64-oc GEMM chunk: acc[4] (oc = ocb + (tid>>5)*4 + j), px-pair = tid&31.
// Wd: dup'd transposed weights, row stride ldw (float2 units). srcf: smem float2 [c][p2].
__device__ __forceinline__ void gemm64(const float2* __restrict__ Wd, int ldw, int ocb,
                                       const float* __restrict__ srcf, ULL* acc, int tid)
{
    const int po2 = tid & 31;
    const int ocg = tid >> 5;
    const float2* Wp = Wd + ocb + ocg * 4;
    acc[0] = acc[1] = acc[2] = acc[3] = 0ull;
    #pragma unroll 4
    for (int c = 0; c < CDIM; ++c) {
        ulonglong2 w0 = *(const ulonglong2*)(Wp);
        ulonglong2 w1 = *(const ulonglong2*)(Wp + 2);
        ULL xv = *(const ULL*)(srcf + (c * 32 + po2) * 2);
        ffma2(acc[0], w0.x, xv);
        ffma2(acc[1], w0.y, xv);
        ffma2(acc[2], w1.x, xv);
        ffma2(acc[3], w1.y, xv);
        Wp += ldw;
    }
}

__global__ __launch_bounds__(512, 1)
void win_attn_kernel(const float* __restrict__ x,
                     const float* __restrict__ dw_w,
                     const float* __restrict__ temperature,
                     float* __restrict__ out)
{
    extern __shared__ float smf[];
    float* xsf = smf + XS_OFF;
    float* qsf = smf + QS_OFF;
    float* stf = smf + ST_OFF;

    const int tid = threadIdx.x;
    const int win = blockIdx.x;
    const int b   = win >> 10;
    const int wh  = (win >> 5) & 31;
    const int ww  = win & 31;
    const int h0  = wh * 8 + SHIFT;
    const int w0  = ww * 8 + SHIFT;

    // ---- load x window (applies -SHIFT roll), px-paired: (p2, p2+32) ----
    for (int i = tid; i < CDIM * 32; i += 512) {
        const int ch = i >> 5, p2 = i & 31;
        const int gh  = (h0 + (p2 >> 3)) & 255;
        const int gh2 = (gh + 4) & 255;
        const int gw  = (w0 + (p2 & 7)) & 255;
        const float* base = x + (size_t)(b * CDIM + ch) * HWDIM * HWDIM;
        float2 v = make_float2(base[gh * HWDIM + gw], base[gh2 * HWDIM + gw]);
        *(float2*)(xsf + i * 2) = v;
    }
    __syncthreads();

    const int po2 = tid & 31;
    const int ocg = tid >> 5;
    const int pl  = tid & 63;
    const int cl0 = tid >> 6;          // 0..7
    const int rr0 = pl >> 3, cc0 = pl & 7;

    // ---- qkv 1x1 (576x192 GEMM) + depthwise 3x3, 9 chunks of 64 oc ----
    for (int chk = 0; chk < 9; ++chk) {
        const int ocb = chk * 64;
        ULL acc[4];
        gemm64(g_qkv_wd, OC3, ocb, xsf, acc, tid);
        #pragma unroll
        for (int j = 0; j < 4; ++j)
            *(ULL*)(stf + ((ocg * 4 + j) * 32 + po2) * 2) = acc[j];
        __syncthreads();

        // depthwise 3x3, zero-padded window; px-paired staging layout
        const int wout = ((rr0 & 3) * 8 + cc0) * 2 + (rr0 >> 2);
        for (int it = 0; it < 8; ++it) {
            const int lc = it * 8 + cl0;
            const int gc = ocb + lc;
            const float* wd = dw_w + gc * 9;
            const float* s  = stf + lc * 64;
            float a = 0.f;
            #pragma unroll
            for (int dr = -1; dr <= 1; ++dr) {
                const int rr = rr0 + dr;
                if (rr < 0 || rr > 7) continue;
                #pragma unroll
                for (int dc = -1; dc <= 1; ++dc) {
                    const int c2 = cc0 + dc;
                    if (c2 < 0 || c2 > 7) continue;
                    a += s[((rr & 3) * 8 + c2) * 2 + (rr >> 2)] * wd[(dr + 1) * 3 + dc + 1];
                }
            }
            qsf[gc * 66 + wout] = a;
        }
        __syncthreads();
    }

    // ---- channel attention: 2 warps per head (12 warps active) ----
    const int lane = tid & 31;
    const int widx = tid >> 5;
    float* aof = xsf;   // reuse x region for attention output

    if (widx < 12) {
        const int h = widx >> 1, sub = widx & 1;
        const float* qf = qsf + (h * 32) * 66;
        const float* kf = qsf + (CDIM + h * 32) * 66;
        const float temp = temperature[h];
        float* attn_s = stf + h * 1024;

        // cache k-row(channel=lane) packed; compute q/k norms
        ULL k2[32];
        float sq = 0.f, sk = 0.f;
        #pragma unroll
        for (int n2 = 0; n2 < 32; ++n2) {
            ULL kv = *(const ULL*)(kf + lane * 66 + n2 * 2);
            k2[n2] = kv;
            float2 kk = asf2(kv);
            sk += kk.x * kk.x + kk.y * kk.y;
            float2 qq = *(const float2*)(qf + lane * 66 + n2 * 2);
            sq += qq.x * qq.x + qq.y * qq.y;
        }
        const float rk = 1.f / fmaxf(sqrtf(sk), 1e-12f);
        const float rq = 1.f / fmaxf(sqrtf(sq), 1e-12f);

        for (int r = 0; r < 16; ++r) {
            const int r0 = sub * 16 + r;
            ULL a2 = 0ull;
            #pragma unroll
            for (int n2 = 0; n2 < 32; ++n2) {
                ULL qv = *(const ULL*)(qf + r0 * 66 + n2 * 2);   // broadcast
                ffma2(a2, qv, k2[n2]);
            }
            float2 av = asf2(a2);
            float a = av.x + av.y;
            const float rqr = __shfl_sync(0xffffffffu, rq, r0);
            a *= rqr * rk * temp;
            // softmax across lanes (lane == d)
            float m = a;
            #pragma unroll
            for (int o = 16; o; o >>= 1) m = fmaxf(m, __shfl_xor_sync(0xffffffffu, m, o));
            const float e = __expf(a - m);
            float s2 = e;
            #pragma unroll
            for (int o = 16; o; o >>= 1) s2 += __shfl_xor_sync(0xffffffffu, s2, o);
            attn_s[r0 * 32 + lane] = e / s2;
        }
    }
    __syncthreads();

    if (widx < 12) {
        const int h = widx >> 1, sub = widx & 1;
        const float* vf = qsf + (2 * CDIM + h * 32) * 66;
        const float* attn_s = stf + h * 1024;

        // cache v columns (px-pair = lane) packed
        ULL vc[32];
        #pragma unroll
        for (int d = 0; d < 32; ++d)
            vc[d] = *(const ULL*)(vf + d * 66 + lane * 2);

        for (int r = 0; r < 16; ++r) {
            const int r0 = sub * 16 + r;
            ULL o2 = 0ull;
            #pragma unroll
            for (int d = 0; d < 32; ++d) {
                ULL ad = dup2(attn_s[r0 * 32 + d]);   // broadcast + dup
                ffma2(o2, ad, vc[d]);
            }
            *(ULL*)(aof + ((h * 32 + r0) * 32 + lane) * 2) = o2;
        }
    }
    __syncthreads();

    // ---- project_out 1x1 (192x192 GEMM), 3 chunks of 64, store with +SHIFT roll ----
    for (int chk = 0; chk < 3; ++chk) {
        const int ocb = chk * 64;
        ULL acc[4];
        gemm64(g_proj_wd, CDIM, ocb, aof, acc, tid);
        const int gh  = (h0 + (po2 >> 3)) & 255;
        const int gh2 = (gh + 4) & 255;
        const int gw  = (w0 + (po2 & 7)) & 255;
        #pragma unroll
        for (int j = 0; j < 4; ++j) {
            const int oc = ocb + ocg * 4 + j;
            float2 v = asf2(acc[j]);
            float* base = out + (size_t)(b * CDIM + oc) * HWDIM * HWDIM;
            base[gh * HWDIM + gw]  = v.x;
            base[gh2 * HWDIM + gw] = v.y;
        }
    }
}

extern "C" void kernel_launch(void* const* d_in, const int* in_sizes, int n_in,
                              void* d_out, int out_size)
{
    const float* x           = (const float*)d_in[0];
    const float* qkv_w       = (const float*)d_in[1];
    const float* dw_w        = (const float*)d_in[2];
    const float* proj_w      = (const float*)d_in[3];
    const float* temperature = (const float*)d_in[4];
    float* out               = (float*)d_out;

    const int prep_n = CDIM * OC3 + CDIM * CDIM;
    prep_weights<<<(prep_n + 255) / 256, 256>>>(qkv_w, proj_w);

    const size_t smem_bytes = (size_t)SMEM_FLOATS * sizeof(float);
    cudaFuncSetAttribute(win_attn_kernel,
                         cudaFuncAttributeMaxDynamicSharedMemorySize,
                         (int)smem_bytes);
    win_attn_kernel<<<NWIN, 512, smem_bytes>>>(x, dw_w, temperature, out);
}

// round 6
// speedup vs baseline: 5.8514x; 5.8514x over previous
#include <cuda_runtime.h>
#include <cuda_bf16.h>
#include <cuda_fp16.h>
#include <math.h>
#include <stdint.h>

typedef unsigned long long ULL;
typedef unsigned int u32;
typedef unsigned short u16;

#define CDIM  192
#define HWDIM 256
#define SHIFT 4
#define NWIN  4096

// ---- smem byte offsets ----
// X/AO bf16 planes: b32 words [kpair 96][px stride 72], hi at +0, lo at +27648
#define OFF_X    0
#define PLANE_B  27648
#define OFF_STG  55296            // qkv pre-conv fp16: [576][stride 33 half2] = 76032 B
#define OFF_ATT  55296            // attn mats alias staging (6*1024 f32)
#define OFF_QS   131328           // qkv post-conv fp16: 76032 B
#define SMEM_DYN 207360

// fragment-ordered weights: [mtile 48][kstep 12][hi/lo][lane 32] uint4
// mtiles 0..35 = qkv (576 rows), 36..47 = proj (192 rows)
__device__ uint4 g_wfrag[48 * 12 * 2 * 32];

__device__ __forceinline__ u16 bf16bits(float f) {
    __nv_bfloat16 h = __float2bfloat16(f);
    return *reinterpret_cast<u16*>(&h);
}
__device__ __forceinline__ float bf16val(float f) {
    return __bfloat162float(__float2bfloat16(f));
}

__global__ void prep_wfrag(const float* __restrict__ qkv_w,
                           const float* __restrict__ proj_w)
{
    int idx = blockIdx.x * blockDim.x + threadIdx.x;
    if (idx >= 48 * 12 * 32) return;
    const int mtg = idx / (12 * 32);
    const int ks  = (idx / 32) % 12;
    const int lane = idx & 31;
    const int t = lane & 3, g = lane >> 2;

    uint4 hi4, lo4;
    u32* hp = (u32*)&hi4;
    u32* lp = (u32*)&lo4;
    #pragma unroll
    for (int c2 = 0; c2 < 2; ++c2) {
        #pragma unroll
        for (int r2 = 0; r2 < 2; ++r2) {
            const int row = mtg * 16 + g + r2 * 8;
            const int col = ks * 16 + 2 * t + c2 * 8;
            float w0, w1;
            if (mtg < 36) {
                w0 = qkv_w[row * 192 + col];
                w1 = qkv_w[row * 192 + col + 1];
            } else {
                const int r = row - 576;
                w0 = proj_w[r * 192 + col];
                w1 = proj_w[r * 192 + col + 1];
            }
            const int ri = c2 * 2 + r2;     // a0=(r0,c0) a1=(r1,c0) a2=(r0,c1) a3=(r1,c1)
            hp[ri] = (u32)bf16bits(w0) | ((u32)bf16bits(w1) << 16);
            lp[ri] = (u32)bf16bits(w0 - bf16val(w0)) | ((u32)bf16bits(w1 - bf16val(w1)) << 16);
        }
    }
    g_wfrag[((mtg * 12 + ks) * 2 + 0) * 32 + lane] = hi4;
    g_wfrag[((mtg * 12 + ks) * 2 + 1) * 32 + lane] = lo4;
}

__device__ __forceinline__ void mma16816(float* d, const u32* a, u32 b0, u32 b1)
{
    asm volatile(
        "mma.sync.aligned.m16n8k16.row.col.f32.bf16.bf16.f32 "
        "{%0,%1,%2,%3}, {%4,%5,%6,%7}, {%8,%9}, {%0,%1,%2,%3};"
        : "+f"(d[0]), "+f"(d[1]), "+f"(d[2]), "+f"(d[3])
        : "r"(a[0]), "r"(a[1]), "r"(a[2]), "r"(a[3]), "r"(b0), "r"(b1));
}

__device__ __forceinline__ void ffma2(ULL& d, ULL a, ULL b) {
    asm("fma.rn.f32x2 %0, %1, %2, %0;" : "+l"(d) : "l"(a), "l"(b));
}
__device__ __forceinline__ ULL dup2(float a) {
    ULL r; u32 u = __float_as_uint(a);
    asm("mov.b64 %0, {%1, %1};" : "=l"(r) : "r"(u));
    return r;
}
__device__ __forceinline__ ULL packf2(float2 v) {
    ULL r;
    asm("mov.b64 %0, {%1, %2};" : "=l"(r) : "r"(__float_as_uint(v.x)), "r"(__float_as_uint(v.y)));
    return r;
}
__device__ __forceinline__ float2 asf2(ULL v) {
    float2 f;
    f.x = __uint_as_float((u32)(v & 0xffffffffu));
    f.y = __uint_as_float((u32)(v >> 32));
    return f;
}

__device__ __forceinline__ float conv_at(const float* f, const float* wd, int r, int c)
{
    float a = 0.f;
    #pragma unroll
    for (int dr = -1; dr <= 1; ++dr) {
        int rr = r + dr; if (rr < 0 || rr > 7) continue;
        #pragma unroll
        for (int dc = -1; dc <= 1; ++dc) {
            int cc = c + dc; if (cc < 0 || cc > 7) continue;
            a += f[rr * 8 + cc] * wd[(dr + 1) * 3 + dc + 1];
        }
    }
    return a;
}

__global__ __launch_bounds__(384, 1)
void win_attn_mma(const float* __restrict__ x,
                  const float* __restrict__ dw_w,
                  const float* __restrict__ temperature,
                  float* __restrict__ out)
{
    extern __shared__ char smb[];
    const int tid = threadIdx.x, wid = tid >> 5, lane = tid & 31;
    const int t = lane & 3, g = lane >> 2;
    const int win = blockIdx.x;
    const int b = win >> 10, wh = (win >> 5) & 31, ww = win & 31;
    const int h0 = wh * 8 + SHIFT, w0 = ww * 8 + SHIFT;

    // ---- load x window (-SHIFT roll), split to bf16 hi/lo k-pair-interleaved planes ----
    {
        char* Xp = smb + OFF_X;
        for (int i = tid; i < 1536; i += 384) {          // 96 ch-pairs x 8 rows x 2 quads
            const int c2 = i >> 4, r = (i >> 1) & 7, q = i & 1;
            const int gh = (h0 + r) & 255, gw = (w0 + q * 4) & 255;
            const float* b0p = x + (((size_t)(b * CDIM + 2 * c2)) << 16) + gh * 256 + gw;
            float4 va = *(const float4*)(b0p);
            float4 vb = *(const float4*)(b0p + 65536);
            const float av[4] = {va.x, va.y, va.z, va.w};
            const float bv[4] = {vb.x, vb.y, vb.z, vb.w};
            #pragma unroll
            for (int j = 0; j < 4; ++j) {
                const int px = r * 8 + q * 4 + j;
                const u32 off = (u32)(c2 * 72 + px) * 4u;
                u16 h0b = bf16bits(av[j]);
                u16 h1b = bf16bits(bv[j]);
                *(u32*)(Xp + off) = (u32)h0b | ((u32)h1b << 16);
                u16 l0b = bf16bits(av[j] - bf16val(av[j]));
                u16 l1b = bf16bits(bv[j] - bf16val(bv[j]));
                *(u32*)(Xp + PLANE_B + off) = (u32)l0b | ((u32)l1b << 16);
            }
        }
    }
    __syncthreads();

    const u32 boff = (u32)(t * 288 + g * 4);   // B-frag per-thread byte offset within plane

    // ================= qkv GEMM: warp wid owns rows [wid*48, wid*48+48) =================
    {
        float acc[3][8][4];
        #pragma unroll
        for (int mt = 0; mt < 3; ++mt)
            #pragma unroll
            for (int nt = 0; nt < 8; ++nt)
                #pragma unroll
                for (int i = 0; i < 4; ++i) acc[mt][nt][i] = 0.f;

        #pragma unroll 1
        for (int ks = 0; ks < 12; ++ks) {
            uint4 Ah[3], Al[3];
            #pragma unroll
            for (int mt = 0; mt < 3; ++mt) {
                const int mtg = wid * 3 + mt;
                const uint4* p = g_wfrag + ((mtg * 12 + ks) * 2) * 32 + lane;
                Ah[mt] = p[0];
                Al[mt] = p[32];
            }
            const char* bp = smb + OFF_X + boff + ks * 2304;
            #pragma unroll
            for (int nt = 0; nt < 8; ++nt) {
                const u32 bh0 = *(const u32*)(bp + nt * 32);
                const u32 bh1 = *(const u32*)(bp + nt * 32 + 1152);
                const u32 bl0 = *(const u32*)(bp + nt * 32 + PLANE_B);
                const u32 bl1 = *(const u32*)(bp + nt * 32 + 1152 + PLANE_B);
                #pragma unroll
                for (int mt = 0; mt < 3; ++mt) {
                    mma16816(acc[mt][nt], (const u32*)&Ah[mt], bh0, bh1);
                    mma16816(acc[mt][nt], (const u32*)&Ah[mt], bl0, bl1);
                    mma16816(acc[mt][nt], (const u32*)&Al[mt], bh0, bh1);
                }
            }
        }
        // epilogue -> fp16 staging [ch][33 half2]
        __half2* stg = (__half2*)(smb + OFF_STG);
        #pragma unroll
        for (int mt = 0; mt < 3; ++mt) {
            const int ch0 = (wid * 3 + mt) * 16 + g;
            #pragma unroll
            for (int nt = 0; nt < 8; ++nt) {
                stg[ch0 * 33 + nt * 4 + t]       = __floats2half2_rn(acc[mt][nt][0], acc[mt][nt][1]);
                stg[(ch0 + 8) * 33 + nt * 4 + t] = __floats2half2_rn(acc[mt][nt][2], acc[mt][nt][3]);
            }
        }
    }
    __syncthreads();

    // ================= depthwise 3x3 (zero-padded window), registers =================
    {
        const __half2* stg = (const __half2*)(smb + OFF_STG);
        __half2* qs = (__half2*)(smb + OFF_QS);
        #pragma unroll 1
        for (int rnd = 0; rnd < 2; ++rnd) {
            const int ch = tid + rnd * 384;
            if (ch < 576) {
                float wd[9];
                #pragma unroll
                for (int i = 0; i < 9; ++i) wd[i] = dw_w[ch * 9 + i];
                float f[64];
                #pragma unroll
                for (int i = 0; i < 32; ++i) {
                    float2 v = __half22float2(stg[ch * 33 + i]);
                    f[2 * i] = v.x; f[2 * i + 1] = v.y;
                }
                #pragma unroll
                for (int r = 0; r < 8; ++r)
                    #pragma unroll
                    for (int c = 0; c < 8; c += 2) {
                        float o0 = conv_at(f, wd, r, c);
                        float o1 = conv_at(f, wd, r, c + 1);
                        qs[ch * 33 + (r * 8 + c) / 2] = __floats2half2_rn(o0, o1);
                    }
            }
        }
    }
    __syncthreads();

    // ================= channel attention: 2 warps per head =================
    {
        const __half2* qs2 = (const __half2*)(smb + OFF_QS);
        const int h = wid >> 1, sub = wid & 1;
        const __half2* q2 = qs2 + (h * 32) * 33;
        const __half2* k2 = qs2 + (192 + h * 32) * 33;
        const __half2* v2 = qs2 + (384 + h * 32) * 33;
        const float temp = temperature[h];
        float* attn_s = (float*)(smb + OFF_ATT) + h * 1024;

        ULL kr[32];
        float sq = 0.f, sk = 0.f;
        #pragma unroll
        for (int n2 = 0; n2 < 32; ++n2) {
            float2 kv = __half22float2(k2[lane * 33 + n2]);
            kr[n2] = packf2(kv);
            sk += kv.x * kv.x + kv.y * kv.y;
            float2 qv = __half22float2(q2[lane * 33 + n2]);
            sq += qv.x * qv.x + qv.y * qv.y;
        }
        const float rk = 1.f / fmaxf(sqrtf(sk), 1e-12f);
        const float rq = 1.f / fmaxf(sqrtf(sq), 1e-12f);

        for (int r = 0; r < 16; ++r) {
            const int r0 = sub * 16 + r;
            ULL a2 = 0ull;
            #pragma unroll
            for (int n2 = 0; n2 < 32; ++n2)
                ffma2(a2, packf2(__half22float2(q2[r0 * 33 + n2])), kr[n2]);
            float2 av = asf2(a2);
            float a = av.x + av.y;
            a *= __shfl_sync(0xffffffffu, rq, r0) * rk * temp;
            float m = a;
            #pragma unroll
            for (int o = 16; o; o >>= 1) m = fmaxf(m, __shfl_xor_sync(0xffffffffu, m, o));
            const float e = __expf(a - m);
            float s2 = e;
            #pragma unroll
            for (int o = 16; o; o >>= 1) s2 += __shfl_xor_sync(0xffffffffu, s2, o);
            attn_s[r0 * 32 + lane] = e / s2;
        }
        __syncwarp();

        // out = attn @ v -> AO bf16 hi/lo planes (k-pair-interleaved, px stride 72)
        ULL vc[32];
        #pragma unroll
        for (int d2 = 0; d2 < 32; ++d2)
            vc[d2] = packf2(__half22float2(v2[d2 * 33 + lane]));
        char* Xp = smb + OFF_X;
        for (int r = 0; r < 16; ++r) {
            const int r0 = sub * 16 + r;
            ULL o2 = 0ull;
            #pragma unroll
            for (int d2 = 0; d2 < 32; ++d2)
                ffma2(o2, dup2(attn_s[r0 * 32 + d2]), vc[d2]);
            float2 o = asf2(o2);
            const int ch = h * 32 + r0;
            const u32 base = (u32)((ch >> 1) * 72) * 4u + (u32)((ch & 1) * 2);
            const int px0 = 2 * lane;
            *(u16*)(Xp + base + (px0) * 4)               = bf16bits(o.x);
            *(u16*)(Xp + PLANE_B + base + (px0) * 4)     = bf16bits(o.x - bf16val(o.x));
            *(u16*)(Xp + base + (px0 + 1) * 4)           = bf16bits(o.y);
            *(u16*)(Xp + PLANE_B + base + (px0 + 1) * 4) = bf16bits(o.y - bf16val(o.y));
        }
    }
    __syncthreads();

    // ================= proj GEMM: warp wid owns rows [wid*16, wid*16+16) =================
    {
        float acc[8][4];
        #pragma unroll
        for (int nt = 0; nt < 8; ++nt)
            #pragma unroll
            for (int i = 0; i < 4; ++i) acc[nt][i] = 0.f;

        #pragma unroll 1
        for (int ks = 0; ks < 12; ++ks) {
            const int mtg = 36 + wid;
            const uint4* p = g_wfrag + ((mtg * 12 + ks) * 2) * 32 + lane;
            uint4 Ah = p[0];
            uint4 Al = p[32];
            const char* bp = smb + OFF_X + boff + ks * 2304;
            #pragma unroll
            for (int nt = 0; nt < 8; ++nt) {
                const u32 bh0 = *(const u32*)(bp + nt * 32);
                const u32 bh1 = *(const u32*)(bp + nt * 32 + 1152);
                const u32 bl0 = *(const u32*)(bp + nt * 32 + PLANE_B);
                const u32 bl1 = *(const u32*)(bp + nt * 32 + 1152 + PLANE_B);
                mma16816(acc[nt], (const u32*)&Ah, bh0, bh1);
                mma16816(acc[nt], (const u32*)&Ah, bl0, bl1);
                mma16816(acc[nt], (const u32*)&Al, bh0, bh1);
            }
        }
        // direct store with +SHIFT roll; px = nt*8 + 2t (+1) -> row nt, cols 2t..2t+1
        const int oc0 = wid * 16 + g;
        const int gwp = (w0 + 2 * t) & 255;
        #pragma unroll
        for (int nt = 0; nt < 8; ++nt) {
            const int gh = (h0 + nt) & 255;
            float* p0 = out + (((size_t)(b * CDIM + oc0)) << 16) + gh * 256 + gwp;
            *(float2*)p0 = make_float2(acc[nt][0], acc[nt][1]);
            float* p1 = p0 + (size_t)8 * 65536;
            *(float2*)p1 = make_float2(acc[nt][2], acc[nt][3]);
        }
    }
}

extern "C" void kernel_launch(void* const* d_in, const int* in_sizes, int n_in,
                              void* d_out, int out_size)
{
    const float* x           = (const float*)d_in[0];
    const float* qkv_w       = (const float*)d_in[1];
    const float* dw_w        = (const float*)d_in[2];
    const float* proj_w      = (const float*)d_in[3];
    const float* temperature = (const float*)d_in[4];
    float* out               = (float*)d_out;

    prep_wfrag<<<(48 * 12 * 32 + 255) / 256, 256>>>(qkv_w, proj_w);

    cudaFuncSetAttribute(win_attn_mma, cudaFuncAttributeMaxDynamicSharedMemorySize, SMEM_DYN);
    win_attn_mma<<<NWIN, 384, SMEM_DYN>>>(x, dw_w, temperature, out);
}

// round 7
// speedup vs baseline: 10.0731x; 1.7215x over previous
#include <cuda_runtime.h>
#include <cuda_fp16.h>
#include <math.h>
#include <stdint.h>

typedef unsigned int u32;
typedef unsigned short u16;

#define CDIM  192
#define HWDIM 256
#define SHIFT 4
#define NWIN  4096

// ---- smem byte offsets ----
// X/AO fp16 plane: u32 words [kpair 96][px stride 72] = 27648 B
// STG/QS: qkv staging + post-conv q,k fp16: [576ch][33 h2-words] = 76032 B (in-place conv)
// VT: v transposed [px 64][u32 stride 99] = 25344 B, aliases v-channel staging (stg+50688)
// NRM: [6 heads][2][32] f32 norms = 1536 B
#define OFF_X    0
#define OFF_STG  27648
#define OFF_VT   (27648 + 50688)
#define OFF_NRM  (27648 + 76032)
#define SMEM_DYN (27648 + 76032 + 1536)     // 105216 B -> 2 CTAs/SM

// fragment-ordered fp16 weights: [mtile 48][kstep 12][hi/lo][lane 32] uint4
// mtiles 0..35 = qkv (576 rows), 36..47 = proj (192 rows)
__device__ uint4 g_wfrag[48 * 12 * 2 * 32];

__device__ __forceinline__ u16 f16b(float f) {
    __half h = __float2half_rn(f);
    return *reinterpret_cast<u16*>(&h);
}
__device__ __forceinline__ float f16v(float f) {
    return __half2float(__float2half_rn(f));
}
__device__ __forceinline__ u32 packh2(float a, float b) {
    __half2 h = __floats2half2_rn(a, b);
    return *reinterpret_cast<u32*>(&h);
}
__device__ __forceinline__ float2 h2f2(u32 w) {
    __half2 h = *reinterpret_cast<__half2*>(&w);
    return __half22float2(h);
}

__global__ void prep_wfrag(const float* __restrict__ qkv_w,
                           const float* __restrict__ proj_w)
{
    int idx = blockIdx.x * blockDim.x + threadIdx.x;
    if (idx >= 48 * 12 * 32) return;
    const int mtg = idx / (12 * 32);
    const int ks  = (idx / 32) % 12;
    const int lane = idx & 31;
    const int t = lane & 3, g = lane >> 2;

    uint4 hi4, lo4;
    u32* hp = (u32*)&hi4;
    u32* lp = (u32*)&lo4;
    #pragma unroll
    for (int c2 = 0; c2 < 2; ++c2) {
        #pragma unroll
        for (int r2 = 0; r2 < 2; ++r2) {
            const int row = mtg * 16 + g + r2 * 8;
            const int col = ks * 16 + 2 * t + c2 * 8;
            float w0, w1;
            if (mtg < 36) {
                w0 = qkv_w[row * 192 + col];
                w1 = qkv_w[row * 192 + col + 1];
            } else {
                const int r = row - 576;
                w0 = proj_w[r * 192 + col];
                w1 = proj_w[r * 192 + col + 1];
            }
            const int ri = c2 * 2 + r2;
            hp[ri] = (u32)f16b(w0) | ((u32)f16b(w1) << 16);
            lp[ri] = (u32)f16b(w0 - f16v(w0)) | ((u32)f16b(w1 - f16v(w1)) << 16);
        }
    }
    g_wfrag[((mtg * 12 + ks) * 2 + 0) * 32 + lane] = hi4;
    g_wfrag[((mtg * 12 + ks) * 2 + 1) * 32 + lane] = lo4;
}

__device__ __forceinline__ void mma_h(float* d, const u32* a, u32 b0, u32 b1)
{
    asm volatile(
        "mma.sync.aligned.m16n8k16.row.col.f32.f16.f16.f32 "
        "{%0,%1,%2,%3}, {%4,%5,%6,%7}, {%8,%9}, {%0,%1,%2,%3};"
        : "+f"(d[0]), "+f"(d[1]), "+f"(d[2]), "+f"(d[3])
        : "r"(a[0]), "r"(a[1]), "r"(a[2]), "r"(a[3]), "r"(b0), "r"(b1));
}

__global__ __launch_bounds__(384, 2)
void win_attn_mma(const float* __restrict__ x,
                  const float* __restrict__ dw_w,
                  const float* __restrict__ temperature,
                  float* __restrict__ out)
{
    extern __shared__ char smb[];
    u32* X    = (u32*)(smb + OFF_X);
    u32* stg  = (u32*)(smb + OFF_STG);
    u32* vt   = (u32*)(smb + OFF_VT);
    float* nrm = (float*)(smb + OFF_NRM);

    const int tid = threadIdx.x, wid = tid >> 5, lane = tid & 31;
    const int t = lane & 3, g = lane >> 2;
    const int win = blockIdx.x;
    const int b = win >> 10, wh = (win >> 5) & 31, ww = win & 31;
    const int h0 = wh * 8 + SHIFT, w0 = ww * 8 + SHIFT;

    // ---- load x window (-SHIFT roll) -> fp16 plane [kpair][px stride 72] ----
    for (int i = tid; i < 1536; i += 384) {           // 96 ch-pairs x 8 rows x 2 quads
        const int c2 = i >> 4, r = (i >> 1) & 7, q = i & 1;
        const int gh = (h0 + r) & 255, gw = (w0 + q * 4) & 255;
        const float* p0 = x + (((size_t)(b * CDIM + 2 * c2)) << 16) + gh * 256 + gw;
        float4 va = *(const float4*)(p0);
        float4 vb = *(const float4*)(p0 + 65536);
        const float av[4] = {va.x, va.y, va.z, va.w};
        const float bv[4] = {vb.x, vb.y, vb.z, vb.w};
        #pragma unroll
        for (int j = 0; j < 4; ++j) {
            const int px = r * 8 + q * 4 + j;
            X[c2 * 72 + px] = (u32)f16b(av[j]) | ((u32)f16b(bv[j]) << 16);
        }
    }
    __syncthreads();

    // ================= qkv GEMM: 3 M-passes of 16 rows per warp =================
    #pragma unroll 1
    for (int p = 0; p < 3; ++p) {
        float acc[8][4];
        #pragma unroll
        for (int nt = 0; nt < 8; ++nt)
            #pragma unroll
            for (int i = 0; i < 4; ++i) acc[nt][i] = 0.f;

        const int mtg = wid * 3 + p;
        #pragma unroll 1
        for (int ks = 0; ks < 12; ++ks) {
            const uint4* wp = g_wfrag + ((mtg * 12 + ks) * 2) * 32 + lane;
            uint4 Ah = wp[0];
            uint4 Al = wp[32];
            const int base = (8 * ks + t) * 72 + g;
            #pragma unroll
            for (int nt = 0; nt < 8; ++nt) {
                const u32 b0 = X[base + 8 * nt];
                const u32 b1 = X[base + 8 * nt + 288];
                mma_h(acc[nt], (const u32*)&Ah, b0, b1);
                mma_h(acc[nt], (const u32*)&Al, b0, b1);
            }
        }
        const int ch0 = wid * 48 + p * 16 + g;
        #pragma unroll
        for (int nt = 0; nt < 8; ++nt) {
            stg[ch0 * 33 + nt * 4 + t]       = packh2(acc[nt][0], acc[nt][1]);
            stg[(ch0 + 8) * 33 + nt * 4 + t] = packh2(acc[nt][2], acc[nt][3]);
        }
    }
    __syncthreads();

    // ================= depthwise 3x3 =================
    // q,k channels (0..383): in-place rolling conv, ch = tid
    {
        const int ch = tid;
        float wd[9];
        #pragma unroll
        for (int i = 0; i < 9; ++i) wd[i] = dw_w[ch * 9 + i];
        float rm1[8], rc[8], rp1[8];
        #pragma unroll
        for (int j = 0; j < 8; ++j) rm1[j] = 0.f;
        #pragma unroll
        for (int i = 0; i < 4; ++i) {
            float2 v = h2f2(stg[ch * 33 + i]);
            rc[2 * i] = v.x; rc[2 * i + 1] = v.y;
        }
        #pragma unroll
        for (int r = 0; r < 8; ++r) {
            if (r < 7) {
                #pragma unroll
                for (int i = 0; i < 4; ++i) {
                    float2 v = h2f2(stg[ch * 33 + (r + 1) * 4 + i]);
                    rp1[2 * i] = v.x; rp1[2 * i + 1] = v.y;
                }
            } else {
                #pragma unroll
                for (int j = 0; j < 8; ++j) rp1[j] = 0.f;
            }
            float o[8];
            #pragma unroll
            for (int c = 0; c < 8; ++c) {
                float a = rm1[c] * wd[1] + rc[c] * wd[4] + rp1[c] * wd[7];
                if (c > 0) a += rm1[c - 1] * wd[0] + rc[c - 1] * wd[3] + rp1[c - 1] * wd[6];
                if (c < 7) a += rm1[c + 1] * wd[2] + rc[c + 1] * wd[5] + rp1[c + 1] * wd[8];
                o[c] = a;
            }
            #pragma unroll
            for (int i = 0; i < 4; ++i)
                stg[ch * 33 + r * 4 + i] = packh2(o[2 * i], o[2 * i + 1]);
            #pragma unroll
            for (int j = 0; j < 8; ++j) { rm1[j] = rc[j]; rc[j] = rp1[j]; }
        }
    }
    // v channels (384..575): register-stage, barrier, conv -> transposed vt
    {
        u32 s[32];
        if (tid < 192) {
            const int vch = 384 + tid;
            #pragma unroll
            for (int i = 0; i < 32; ++i) s[i] = stg[vch * 33 + i];
        }
        __syncthreads();
        if (tid < 192) {
            const int vch = 384 + tid;
            float wd[9];
            #pragma unroll
            for (int i = 0; i < 9; ++i) wd[i] = dw_w[vch * 9 + i];
            float rm1[8], rc[8], rp1[8];
            #pragma unroll
            for (int j = 0; j < 8; ++j) rm1[j] = 0.f;
            #pragma unroll
            for (int i = 0; i < 4; ++i) {
                float2 v = h2f2(s[i]);
                rc[2 * i] = v.x; rc[2 * i + 1] = v.y;
            }
            const u32 half_off = (u32)(tid & 1) * 2u;
            const u32 word_off = (u32)(tid >> 1);
            #pragma unroll
            for (int r = 0; r < 8; ++r) {
                if (r < 7) {
                    #pragma unroll
                    for (int i = 0; i < 4; ++i) {
                        float2 v = h2f2(s[(r + 1) * 4 + i]);
                        rp1[2 * i] = v.x; rp1[2 * i + 1] = v.y;
                    }
                } else {
                    #pragma unroll
                    for (int j = 0; j < 8; ++j) rp1[j] = 0.f;
                }
                #pragma unroll
                for (int c = 0; c < 8; ++c) {
                    float a = rm1[c] * wd[1] + rc[c] * wd[4] + rp1[c] * wd[7];
                    if (c > 0) a += rm1[c - 1] * wd[0] + rc[c - 1] * wd[3] + rp1[c - 1] * wd[6];
                    if (c < 7) a += rm1[c + 1] * wd[2] + rc[c + 1] * wd[5] + rp1[c + 1] * wd[8];
                    const int px = r * 8 + c;
                    *(u16*)((char*)vt + ((u32)px * 99u + word_off) * 4u + half_off) = f16b(a);
                }
                #pragma unroll
                for (int j = 0; j < 8; ++j) { rm1[j] = rc[j]; rc[j] = rp1[j]; }
            }
        }
    }
    __syncthreads();

    // ================= attention (tensor-core): 2 warps per head =================
    const int h = wid >> 1, sub = wid & 1;
    {
        // norms: sub0 -> q rows, sub1 -> k rows (lane = channel)
        const int nch = (sub ? 192 : 0) + h * 32 + lane;
        float ss = 0.f;
        #pragma unroll
        for (int i = 0; i < 32; ++i) {
            float2 v = h2f2(stg[nch * 33 + i]);
            ss += v.x * v.x + v.y * v.y;
        }
        nrm[(h * 2 + sub) * 32 + lane] = 1.f / fmaxf(sqrtf(ss), 1e-12f);
    }
    __syncthreads();

    u32 pr[8];   // fp16x2 attn probs for this thread (rows g, g+8 x 4 ntiles)
    {
        // QK^T: rows = q channels sub*16.., cols = k channels 0..31
        float qk[4][4];
        #pragma unroll
        for (int nt = 0; nt < 4; ++nt)
            #pragma unroll
            for (int i = 0; i < 4; ++i) qk[nt][i] = 0.f;
        const int qrow = h * 32 + sub * 16;
        #pragma unroll
        for (int ks = 0; ks < 4; ++ks) {
            u32 a[4];
            const int aw = (qrow + g) * 33 + ks * 8 + t;
            a[0] = stg[aw];
            a[1] = stg[aw + 8 * 33];
            a[2] = stg[aw + 4];
            a[3] = stg[aw + 8 * 33 + 4];
            #pragma unroll
            for (int nt = 0; nt < 4; ++nt) {
                const int bw = (192 + h * 32 + nt * 8 + g) * 33 + ks * 8 + t;
                mma_h(qk[nt], a, stg[bw], stg[bw + 4]);
            }
        }
        // scale by rq*rk*temp, softmax over k-channel dim
        const float temp = temperature[h];
        const float rqA = nrm[h * 64 + sub * 16 + g] * temp;
        const float rqB = nrm[h * 64 + sub * 16 + g + 8] * temp;
        float vA[8], vB[8];
        #pragma unroll
        for (int nt = 0; nt < 4; ++nt) {
            const float rk0 = nrm[h * 64 + 32 + nt * 8 + 2 * t];
            const float rk1 = nrm[h * 64 + 32 + nt * 8 + 2 * t + 1];
            vA[2 * nt]     = qk[nt][0] * rqA * rk0;
            vA[2 * nt + 1] = qk[nt][1] * rqA * rk1;
            vB[2 * nt]     = qk[nt][2] * rqB * rk0;
            vB[2 * nt + 1] = qk[nt][3] * rqB * rk1;
        }
        float mA = vA[0], mB = vB[0];
        #pragma unroll
        for (int i = 1; i < 8; ++i) { mA = fmaxf(mA, vA[i]); mB = fmaxf(mB, vB[i]); }
        #pragma unroll
        for (int o = 1; o <= 2; o <<= 1) {
            mA = fmaxf(mA, __shfl_xor_sync(0xffffffffu, mA, o));
            mB = fmaxf(mB, __shfl_xor_sync(0xffffffffu, mB, o));
        }
        float sA = 0.f, sB = 0.f;
        #pragma unroll
        for (int i = 0; i < 8; ++i) {
            vA[i] = __expf(vA[i] - mA); sA += vA[i];
            vB[i] = __expf(vB[i] - mB); sB += vB[i];
        }
        #pragma unroll
        for (int o = 1; o <= 2; o <<= 1) {
            sA += __shfl_xor_sync(0xffffffffu, sA, o);
            sB += __shfl_xor_sync(0xffffffffu, sB, o);
        }
        const float iA = 1.f / sA, iB = 1.f / sB;
        #pragma unroll
        for (int nt = 0; nt < 4; ++nt) {
            pr[nt]     = packh2(vA[2 * nt] * iA, vA[2 * nt + 1] * iA);
            pr[4 + nt] = packh2(vB[2 * nt] * iB, vB[2 * nt + 1] * iB);
        }
    }
    __syncthreads();   // all QK reads of q-region done before aliasing att over it

    // store attn probs fp16 into (dead) q-staging region: [head][row 32][stride 17 u32]
    const int attb = h * 1056;
    {
        const int row = sub * 16 + g;
        #pragma unroll
        for (int nt = 0; nt < 4; ++nt) {
            stg[attb + row * 17 + nt * 4 + t]       = pr[nt];
            stg[attb + (row + 8) * 17 + nt * 4 + t] = pr[4 + nt];
        }
    }
    __syncthreads();

    // attn @ v: M=32 out-channels, N=64 px (warp sub covers px sub*32..), K=32
    {
        float av[2][4][4];
        #pragma unroll
        for (int mt = 0; mt < 2; ++mt)
            #pragma unroll
            for (int nt = 0; nt < 4; ++nt)
                #pragma unroll
                for (int i = 0; i < 4; ++i) av[mt][nt][i] = 0.f;

        #pragma unroll
        for (int ks2 = 0; ks2 < 2; ++ks2) {
            u32 bb[4][2];
            #pragma unroll
            for (int nt = 0; nt < 4; ++nt) {
                const int px = sub * 32 + nt * 8 + g;
                const int bw = px * 99 + h * 16 + ks2 * 8 + t;
                bb[nt][0] = vt[bw];
                bb[nt][1] = vt[bw + 4];
            }
            #pragma unroll
            for (int mt = 0; mt < 2; ++mt) {
                u32 a[4];
                const int aw = attb + (mt * 16 + g) * 17 + ks2 * 8 + t;
                a[0] = stg[aw];
                a[1] = stg[aw + 8 * 17];
                a[2] = stg[aw + 4];
                a[3] = stg[aw + 8 * 17 + 4];
                #pragma unroll
                for (int nt = 0; nt < 4; ++nt)
                    mma_h(av[mt][nt], a, bb[nt][0], bb[nt][1]);
            }
        }
        // epilogue -> AO fp16 plane (X region): u16 scatter by channel parity
        #pragma unroll
        for (int mt = 0; mt < 2; ++mt) {
            const int chA = h * 32 + mt * 16 + g;
            const int chB = chA + 8;
            #pragma unroll
            for (int nt = 0; nt < 4; ++nt) {
                const int px0 = sub * 32 + nt * 8 + 2 * t;
                *(u16*)((char*)X + ((chA >> 1) * 72 + px0) * 4 + (chA & 1) * 2)     = f16b(av[mt][nt][0]);
                *(u16*)((char*)X + ((chA >> 1) * 72 + px0 + 1) * 4 + (chA & 1) * 2) = f16b(av[mt][nt][1]);
                *(u16*)((char*)X + ((chB >> 1) * 72 + px0) * 4 + (chB & 1) * 2)     = f16b(av[mt][nt][2]);
                *(u16*)((char*)X + ((chB >> 1) * 72 + px0 + 1) * 4 + (chB & 1) * 2) = f16b(av[mt][nt][3]);
            }
        }
    }
    __syncthreads();

    // ================= proj GEMM: warp owns rows wid*16..+16, direct store =================
    {
        float acc[8][4];
        #pragma unroll
        for (int nt = 0; nt < 8; ++nt)
            #pragma unroll
            for (int i = 0; i < 4; ++i) acc[nt][i] = 0.f;

        const int mtg = 36 + wid;
        #pragma unroll 1
        for (int ks = 0; ks < 12; ++ks) {
            const uint4* wp = g_wfrag + ((mtg * 12 + ks) * 2) * 32 + lane;
            uint4 Ah = wp[0];
            uint4 Al = wp[32];
            const int base = (8 * ks + t) * 72 + g;
            #pragma unroll
            for (int nt = 0; nt < 8; ++nt) {
                const u32 b0 = X[base + 8 * nt];
                const u32 b1 = X[base + 8 * nt + 288];
                mma_h(acc[nt], (const u32*)&Ah, b0, b1);
                mma_h(acc[nt], (const u32*)&Al, b0, b1);
            }
        }
        const int oc0 = wid * 16 + g;
        const int gwp = (w0 + 2 * t) & 255;
        #pragma unroll
        for (int nt = 0; nt < 8; ++nt) {
            const int gh = (h0 + nt) & 255;
            float* p0 = out + (((size_t)(b * CDIM + oc0)) << 16) + gh * 256 + gwp;
            *(float2*)p0 = make_float2(acc[nt][0], acc[nt][1]);
            float* p1 = p0 + (size_t)8 * 65536;
            *(float2*)p1 = make_float2(acc[nt][2], acc[nt][3]);
        }
    }
}

extern "C" void kernel_launch(void* const* d_in, const int* in_sizes, int n_in,
                              void* d_out, int out_size)
{
    const float* x           = (const float*)d_in[0];
    const float* qkv_w       = (const float*)d_in[1];
    const float* dw_w        = (const float*)d_in[2];
    const float* proj_w      = (const float*)d_in[3];
    const float* temperature = (const float*)d_in[4];
    float* out               = (float*)d_out;

    prep_wfrag<<<(48 * 12 * 32 + 255) / 256, 256>>>(qkv_w, proj_w);

    cudaFuncSetAttribute(win_attn_mma, cudaFuncAttributeMaxDynamicSharedMemorySize, SMEM_DYN);
    win_attn_mma<<<NWIN, 384, SMEM_DYN>>>(x, dw_w, temperature, out);
}